// round 2
// baseline (speedup 1.0000x reference)
#include <cuda_runtime.h>
#include <math.h>

// Problem constants
#define Bsz 16
#define Lsz 2048
#define BLn (Bsz*Lsz)          // 32768 (b,l) positions
#define DI 256                 // d_inner
#define DS 16                  // d_state
#define NCH 32                 // scan chunks
#define CLEN (Lsz/NCH)         // 64 steps per chunk

// ---------------- scratch (static device globals; no allocation) ----------------
static __device__ float g_xcraw[BLn*DI];   // in_proj x-half (pre conv)
static __device__ float g_gate [BLn*DI];   // silu(z)
static __device__ float g_xc   [BLn*DI];   // silu(conv(x))
static __device__ float g_delta[BLn*DI];   // softplus(dt_proj)
static __device__ float g_Bm   [BLn*DS];
static __device__ float g_Cm   [BLn*DS];
static __device__ float g_P    [Bsz*DI*NCH*DS];  // chunk cum-prod of dA
static __device__ float g_hl   [Bsz*DI*NCH*DS];  // chunk-local h (h_in = 0)
static __device__ float g_S    [Bsz*DI*NCH*DS];  // sum_t g*C*cumA
static __device__ float g_accl [Bsz*DI*NCH];     // chunk-local gated y accum
static __device__ float g_acc  [Bsz*DI];         // final per-channel sums

__device__ __forceinline__ float silu_f(float x){ return x / (1.0f + __expf(-x)); }
__device__ __forceinline__ float softplus_f(float x){ return (x > 20.0f) ? x : log1pf(__expf(x)); }

// ---------------- K1: embedding gather + in_proj GEMM (+ SiLU on z half) ----------------
// out[m,n] = sum_k emb[ids[m],k] * W[n,k];  M=32768, N=512, K=128
// Tile: 128x128, BK=16, 256 threads, 8x8 micro-tile (fragments split 4 + 4@+64
// to keep LDS.128 conflicts <= 2-way).
__global__ void __launch_bounds__(256) k1_inproj(const int* __restrict__ ids,
                                                 const float* __restrict__ emb,
                                                 const float* __restrict__ wproj)
{
    __shared__ __align__(16) float As[16][132];
    __shared__ __align__(16) float Ws[16][132];
    __shared__ int sids[128];
    const int tid = threadIdx.x;
    const int m0 = blockIdx.x * 128;
    const int n0 = blockIdx.y * 128;
    if (tid < 128) sids[tid] = ids[m0 + tid];
    __syncthreads();

    float acc[8][8];
#pragma unroll
    for (int i = 0; i < 8; i++)
#pragma unroll
        for (int j = 0; j < 8; j++) acc[i][j] = 0.0f;

    const int tx = tid & 15, ty = tid >> 4;

#pragma unroll 1
    for (int k0 = 0; k0 < 128; k0 += 16){
#pragma unroll
        for (int i = 0; i < 8; i++){
            int e  = i * 256 + tid;       // 0..2047
            int r  = e >> 4;              // row in tile (0..127)
            int kk = e & 15;              // k within BK
            As[kk][r] = __ldg(emb + sids[r] * 128 + k0 + kk);
            Ws[kk][r] = __ldg(wproj + (n0 + r) * 128 + k0 + kk);
        }
        __syncthreads();
#pragma unroll
        for (int kk = 0; kk < 16; kk++){
            float4 a0 = *(const float4*)(&As[kk][ty * 4]);
            float4 a1 = *(const float4*)(&As[kk][64 + ty * 4]);
            float4 b0 = *(const float4*)(&Ws[kk][tx * 4]);
            float4 b1 = *(const float4*)(&Ws[kk][64 + tx * 4]);
            float av[8] = {a0.x,a0.y,a0.z,a0.w,a1.x,a1.y,a1.z,a1.w};
            float bv[8] = {b0.x,b0.y,b0.z,b0.w,b1.x,b1.y,b1.z,b1.w};
#pragma unroll
            for (int i = 0; i < 8; i++)
#pragma unroll
                for (int j = 0; j < 8; j++)
                    acc[i][j] = fmaf(av[i], bv[j], acc[i][j]);
        }
        __syncthreads();
    }

    // rows: i<4 -> ty*4+i ; i>=4 -> 64+ty*4+(i-4)
    // cols: j<4 -> n0+tx*4+j ; j>=4 -> n0+64+tx*4+(j-4)
#pragma unroll
    for (int i = 0; i < 8; i++){
        int m = m0 + ((i < 4) ? (ty * 4 + i) : (64 + ty * 4 + i - 4));
        if (n0 < 256){
            float4 o0 = make_float4(acc[i][0], acc[i][1], acc[i][2], acc[i][3]);
            float4 o1 = make_float4(acc[i][4], acc[i][5], acc[i][6], acc[i][7]);
            *(float4*)(g_xcraw + m * 256 + n0 + tx * 4)      = o0;
            *(float4*)(g_xcraw + m * 256 + n0 + 64 + tx * 4) = o1;
        } else {
            int nz = n0 - 256;
            float4 o0 = make_float4(silu_f(acc[i][0]), silu_f(acc[i][1]),
                                    silu_f(acc[i][2]), silu_f(acc[i][3]));
            float4 o1 = make_float4(silu_f(acc[i][4]), silu_f(acc[i][5]),
                                    silu_f(acc[i][6]), silu_f(acc[i][7]));
            *(float4*)(g_gate + m * 256 + nz + tx * 4)      = o0;
            *(float4*)(g_gate + m * 256 + nz + 64 + tx * 4) = o1;
        }
    }
}

// ---------------- K2: depthwise causal conv (D_CONV=4) + bias + SiLU ----------------
__global__ void __launch_bounds__(256) k2_conv(const float* __restrict__ conv_w,
                                               const float* __restrict__ conv_b)
{
    int idx = blockIdx.x * 256 + threadIdx.x;     // over BLn * 64 float4 groups
    int d4 = idx & 63;
    int bl = idx >> 6;
    int l  = bl & (Lsz - 1);
    int d  = d4 << 2;

    float w[4][4];
#pragma unroll
    for (int q = 0; q < 4; q++){
        float4 wq = __ldg((const float4*)(conv_w + (d + q) * 4));
        w[q][0] = wq.x; w[q][1] = wq.y; w[q][2] = wq.z; w[q][3] = wq.w;
    }
    float4 bb = __ldg((const float4*)(conv_b + d));
    float a0 = bb.x, a1 = bb.y, a2 = bb.z, a3 = bb.w;

#pragma unroll
    for (int k = 0; k < 4; k++){
        int lk = l - 3 + k;
        if (lk >= 0){
            float4 v = *(const float4*)(g_xcraw + (bl - 3 + k) * 256 + d);
            a0 = fmaf(w[0][k], v.x, a0);
            a1 = fmaf(w[1][k], v.y, a1);
            a2 = fmaf(w[2][k], v.z, a2);
            a3 = fmaf(w[3][k], v.w, a3);
        }
    }
    float4 o;
    o.x = silu_f(a0); o.y = silu_f(a1); o.z = silu_f(a2); o.w = silu_f(a3);
    *(float4*)(g_xc + bl * 256 + d) = o;
}

// ---------------- K3: x_proj (40x256) + dt_proj (256x8) + softplus; emit delta/B/C ----------------
// One warp handles 4 (b,l) positions. Channel assignment d = k*32 + lane (coalesced).
__global__ void __launch_bounds__(256) k3_xproj(const float* __restrict__ xpw,
                                                const float* __restrict__ dtw,
                                                const float* __restrict__ dtb)
{
    __shared__ float sdbc[8][4][40];
    const int lane = threadIdx.x & 31;
    const int wp   = threadIdx.x >> 5;
    const int bl0  = (blockIdx.x * 8 + wp) * 4;

    float xcl[4][8];
#pragma unroll
    for (int p = 0; p < 4; p++)
#pragma unroll
        for (int k = 0; k < 8; k++)
            xcl[p][k] = g_xc[(bl0 + p) * 256 + k * 32 + lane];

#pragma unroll 8
    for (int j = 0; j < 40; j++){
        float wl[8];
#pragma unroll
        for (int k = 0; k < 8; k++) wl[k] = __ldg(xpw + j * 256 + k * 32 + lane);
        float s0 = 0.f, s1 = 0.f, s2 = 0.f, s3 = 0.f;
#pragma unroll
        for (int k = 0; k < 8; k++){
            s0 = fmaf(wl[k], xcl[0][k], s0);
            s1 = fmaf(wl[k], xcl[1][k], s1);
            s2 = fmaf(wl[k], xcl[2][k], s2);
            s3 = fmaf(wl[k], xcl[3][k], s3);
        }
#pragma unroll
        for (int off = 16; off; off >>= 1){
            s0 += __shfl_xor_sync(0xffffffffu, s0, off);
            s1 += __shfl_xor_sync(0xffffffffu, s1, off);
            s2 += __shfl_xor_sync(0xffffffffu, s2, off);
            s3 += __shfl_xor_sync(0xffffffffu, s3, off);
        }
        if (lane == 0){
            sdbc[wp][0][j] = s0; sdbc[wp][1][j] = s1;
            sdbc[wp][2][j] = s2; sdbc[wp][3][j] = s3;
        }
    }
    __syncwarp();

    if (lane < 16){
#pragma unroll
        for (int p = 0; p < 4; p++){
            g_Bm[(bl0 + p) * 16 + lane] = sdbc[wp][p][8  + lane];
            g_Cm[(bl0 + p) * 16 + lane] = sdbc[wp][p][24 + lane];
        }
    }

#pragma unroll
    for (int k = 0; k < 8; k++){
        int d = k * 32 + lane;
        float4 w0 = __ldg((const float4*)(dtw + d * 8));
        float4 w1 = __ldg((const float4*)(dtw + d * 8 + 4));
        float bias = __ldg(dtb + d);
#pragma unroll
        for (int p = 0; p < 4; p++){
            const float* dv = sdbc[wp][p];
            float t = bias;
            t = fmaf(w0.x, dv[0], t); t = fmaf(w0.y, dv[1], t);
            t = fmaf(w0.z, dv[2], t); t = fmaf(w0.w, dv[3], t);
            t = fmaf(w1.x, dv[4], t); t = fmaf(w1.y, dv[5], t);
            t = fmaf(w1.z, dv[6], t); t = fmaf(w1.w, dv[7], t);
            g_delta[(bl0 + p) * 256 + d] = softplus_f(t);
        }
    }
}

// ---------------- K4: chunked selective scan, pass A ----------------
// Thread (b, chunk c, channel d). Computes chunk-local {P, h_local, S, acc_local}.
// Exploits A[d,n] = r_n * A[d,0] with integer r_n = n+1 (verified at runtime):
// dA_n = e1^(n+1), e1 = exp(delta*A[d,0])  -> 1 MUFU + 15 FMUL per step instead
// of 16 MUFU. Generic-exp fallback if the ratio check fails.
__global__ void __launch_bounds__(256) k4_scan(const float* __restrict__ A_log,
                                               const float* __restrict__ Dvec)
{
    __shared__ __align__(16) float sB[CLEN * 16];
    __shared__ __align__(16) float sC[CLEN * 16];

    const int b = blockIdx.x >> 5;       // NCH = 32
    const int c = blockIdx.x & 31;
    const int d = threadIdx.x;

    const float An0 = -__expf(__ldg(A_log + d * 16));
    bool pw_ok = true;
#pragma unroll
    for (int n = 1; n < 16; n++){
        float Ann = -__expf(__ldg(A_log + d * 16 + n));
        float r = Ann / An0;
        pw_ok = pw_ok && (fabsf(r - (float)(n + 1)) < 1e-3f);
    }
    const float Dd = __ldg(Dvec + d);

    // stage B/C for this chunk in shared memory (8 KB)
    const int l0 = b * Lsz + c * CLEN;
    {
        const float4* gB = (const float4*)(g_Bm + l0 * 16);
        const float4* gC = (const float4*)(g_Cm + l0 * 16);
        ((float4*)sB)[d] = gB[d];
        ((float4*)sC)[d] = gC[d];
    }
    __syncthreads();

    float h[16], P[16], S[16];
#pragma unroll
    for (int n = 0; n < 16; n++){ h[n] = 0.0f; P[n] = 1.0f; S[n] = 0.0f; }
    float accl = 0.0f;

    int base = l0 * 256 + d;

    if (pw_ok){
#pragma unroll 1
        for (int t = 0; t < CLEN; t++){
            float delta = g_delta[base];
            float gv    = g_gate[base];
            float xcv   = g_xc[base];
            float dxv   = delta * xcv;

            float Bv[16], Cv[16];
#pragma unroll
            for (int q = 0; q < 4; q++){
                float4 bb = ((const float4*)sB)[t * 4 + q];
                float4 cc = ((const float4*)sC)[t * 4 + q];
                Bv[q*4+0] = bb.x; Bv[q*4+1] = bb.y; Bv[q*4+2] = bb.z; Bv[q*4+3] = bb.w;
                Cv[q*4+0] = cc.x; Cv[q*4+1] = cc.y; Cv[q*4+2] = cc.z; Cv[q*4+3] = cc.w;
            }

            // dA powers: p[i] = e1^(i+1), log-depth product tree
            float e1 = __expf(delta * An0);
            float p[16];
            p[0] = e1;
#pragma unroll
            for (int i = 1; i < 16; i++) p[i] = p[(i - 1) >> 1] * p[i >> 1];

            float yloc = 0.0f;
#pragma unroll
            for (int n = 0; n < 16; n++){
                P[n] *= p[n];
                h[n] = fmaf(p[n], h[n], dxv * Bv[n]);
                yloc = fmaf(h[n], Cv[n], yloc);
                S[n] = fmaf(P[n], gv * Cv[n], S[n]);
            }
            accl = fmaf(gv, fmaf(xcv, Dd, yloc), accl);
            base += 256;
        }
    } else {
        // cold generic path (reloads A each step; correctness only)
#pragma unroll 1
        for (int t = 0; t < CLEN; t++){
            float delta = g_delta[base];
            float gv    = g_gate[base];
            float xcv   = g_xc[base];
            float dxv   = delta * xcv;
            float yloc  = 0.0f;
#pragma unroll 4
            for (int n = 0; n < 16; n++){
                float An = -__expf(__ldg(A_log + d * 16 + n));
                float dA = __expf(delta * An);
                float Bn = sB[t * 16 + n];
                float Cn = sC[t * 16 + n];
                P[n] *= dA;
                h[n] = fmaf(dA, h[n], dxv * Bn);
                yloc = fmaf(h[n], Cn, yloc);
                S[n] = fmaf(P[n], gv * Cn, S[n]);
            }
            accl = fmaf(gv, fmaf(xcv, Dd, yloc), accl);
            base += 256;
        }
    }

    const int ob = (b * 256 + d) * NCH + c;
    g_accl[ob] = accl;
#pragma unroll
    for (int n = 0; n < 16; n++){
        g_P [ob * 16 + n] = P[n];
        g_hl[ob * 16 + n] = h[n];
        g_S [ob * 16 + n] = S[n];
    }
}

// ---------------- K5: chunk combine (sequential over 32 chunks per (b,d)) ----------------
__global__ void __launch_bounds__(256) k5_combine()
{
    int gid = blockIdx.x * 256 + threadIdx.x;   // (b,d): 0..4095
    float h[16];
#pragma unroll
    for (int n = 0; n < 16; n++) h[n] = 0.0f;
    float acc = 0.0f;
#pragma unroll 1
    for (int c = 0; c < NCH; c++){
        int base = gid * NCH + c;
        acc += g_accl[base];
        const float4* sp = (const float4*)(g_S  + base * 16);
        const float4* pp = (const float4*)(g_P  + base * 16);
        const float4* hp = (const float4*)(g_hl + base * 16);
#pragma unroll
        for (int q = 0; q < 4; q++){
            float4 sv = sp[q], pv = pp[q], hv = hp[q];
            acc = fmaf(h[q*4+0], sv.x, acc);
            acc = fmaf(h[q*4+1], sv.y, acc);
            acc = fmaf(h[q*4+2], sv.z, acc);
            acc = fmaf(h[q*4+3], sv.w, acc);
            h[q*4+0] = fmaf(pv.x, h[q*4+0], hv.x);
            h[q*4+1] = fmaf(pv.y, h[q*4+1], hv.y);
            h[q*4+2] = fmaf(pv.z, h[q*4+2], hv.z);
            h[q*4+3] = fmaf(pv.w, h[q*4+3], hv.w);
        }
    }
    g_acc[gid] = acc;
}

// ---------------- K6: out_proj + mean + classifier ----------------
__global__ void __launch_bounds__(128) k6_head(const float* __restrict__ opw,
                                               const float* __restrict__ clw,
                                               const float* __restrict__ clb,
                                               float* __restrict__ out)
{
    __shared__ float mvec[128];
    int b = blockIdx.x, j = threadIdx.x;
    float s = 0.0f;
    const float* ar = g_acc + b * 256;
#pragma unroll 8
    for (int e = 0; e < 256; e++) s = fmaf(ar[e], __ldg(opw + j * 256 + e), s);
    mvec[j] = s * (1.0f / 2048.0f);
    __syncthreads();
    if (j < 2){
        float t = __ldg(clb + j);
#pragma unroll 8
        for (int e = 0; e < 128; e++) t = fmaf(mvec[e], __ldg(clw + j * 128 + e), t);
        out[b * 2 + j] = t;
    }
}

// ---------------- launch ----------------
extern "C" void kernel_launch(void* const* d_in, const int* in_sizes, int n_in,
                              void* d_out, int out_size)
{
    const int*   ids  = (const int*)  d_in[0];
    const float* emb  = (const float*)d_in[1];
    const float* ipw  = (const float*)d_in[2];
    const float* cw   = (const float*)d_in[3];
    const float* cb   = (const float*)d_in[4];
    const float* xpw  = (const float*)d_in[5];
    const float* dtw  = (const float*)d_in[6];
    const float* dtb  = (const float*)d_in[7];
    const float* alog = (const float*)d_in[8];
    const float* dvec = (const float*)d_in[9];
    const float* opw  = (const float*)d_in[10];
    const float* clw  = (const float*)d_in[11];
    const float* clb  = (const float*)d_in[12];
    float* out = (float*)d_out;

    dim3 g1(BLn / 128, 4);
    k1_inproj<<<g1, 256>>>(ids, emb, ipw);
    k2_conv<<<(BLn * 64) / 256, 256>>>(cw, cb);
    k3_xproj<<<BLn / 32, 256>>>(xpw, dtw, dtb);
    k4_scan<<<Bsz * NCH, 256>>>(alog, dvec);
    k5_combine<<<(Bsz * DI) / 256, 256>>>();
    k6_head<<<Bsz, 128>>>(opw, clw, clb, out);
}

// round 4
// speedup vs baseline: 1.2050x; 1.2050x over previous
#include <cuda_runtime.h>
#include <math.h>

// Problem constants
#define Bsz 16
#define Lsz 2048
#define BLn (Bsz*Lsz)          // 32768 (b,l) positions
#define DI 256                 // d_inner
#define DS 16                  // d_state
#define NCH 32                 // scan chunks
#define CLEN (Lsz/NCH)         // 64 steps per chunk

// ---------------- scratch (static device globals; no allocation) ----------------
static __device__ float  g_xcraw[BLn*DI];   // in_proj x-half (pre conv)
static __device__ float  g_gate [BLn*DI];   // silu(z)
static __device__ float  g_xc   [BLn*DI];   // silu(conv(x))
static __device__ float2 g_dxc  [BLn*DI];   // packed {delta, xc} from K3
static __device__ float  g_Bm   [BLn*DS];
static __device__ float  g_Cm   [BLn*DS];
static __device__ float  g_P    [Bsz*DI*NCH*DS];  // chunk cum-prod of dA
static __device__ float  g_hl   [Bsz*DI*NCH*DS];  // chunk-local h (h_in = 0)
static __device__ float  g_S    [Bsz*DI*NCH*DS];  // sum_t g*C*cumA
static __device__ float  g_accl [Bsz*DI*NCH];     // chunk-local gated y accum
static __device__ float  g_acc  [Bsz*DI];         // final per-channel sums

__device__ __forceinline__ float silu_f(float x){ return x / (1.0f + __expf(-x)); }
__device__ __forceinline__ float softplus_f(float x){ return (x > 20.0f) ? x : log1pf(__expf(x)); }

// ---------------- K1: embedding gather + in_proj GEMM (+ SiLU on z half) ----------------
// out[m,n] = sum_k emb[ids[m],k] * W[n,k];  M=32768, N=512, K=128
// Tile: 128x128, BK=16, 256 threads, 8x8 micro-tile, LDG.128 fills.
__global__ void __launch_bounds__(256) k1_inproj(const int* __restrict__ ids,
                                                 const float* __restrict__ emb,
                                                 const float* __restrict__ wproj)
{
    __shared__ __align__(16) float As[16][132];
    __shared__ __align__(16) float Ws[16][132];
    __shared__ int sids[128];
    const int tid = threadIdx.x;
    const int m0 = blockIdx.x * 128;
    const int n0 = blockIdx.y * 128;
    if (tid < 128) sids[tid] = ids[m0 + tid];
    __syncthreads();

    float acc[8][8];
#pragma unroll
    for (int i = 0; i < 8; i++)
#pragma unroll
        for (int j = 0; j < 8; j++) acc[i][j] = 0.0f;

    const int tx = tid & 15, ty = tid >> 4;

#pragma unroll 1
    for (int k0 = 0; k0 < 128; k0 += 16){
        // fill: 512 float4 per operand, 2 per thread
#pragma unroll
        for (int i = 0; i < 2; i++){
            int idx = i * 256 + tid;        // 0..511
            int r   = idx >> 2;             // row 0..127
            int kq  = (idx & 3) << 2;       // 0,4,8,12
            float4 va = *(const float4*)(emb + sids[r] * 128 + k0 + kq);
            As[kq + 0][r] = va.x; As[kq + 1][r] = va.y;
            As[kq + 2][r] = va.z; As[kq + 3][r] = va.w;
            float4 vw = *(const float4*)(wproj + (n0 + r) * 128 + k0 + kq);
            Ws[kq + 0][r] = vw.x; Ws[kq + 1][r] = vw.y;
            Ws[kq + 2][r] = vw.z; Ws[kq + 3][r] = vw.w;
        }
        __syncthreads();
#pragma unroll
        for (int kk = 0; kk < 16; kk++){
            float4 a0 = *(const float4*)(&As[kk][ty * 4]);
            float4 a1 = *(const float4*)(&As[kk][64 + ty * 4]);
            float4 b0 = *(const float4*)(&Ws[kk][tx * 4]);
            float4 b1 = *(const float4*)(&Ws[kk][64 + tx * 4]);
            float av[8] = {a0.x,a0.y,a0.z,a0.w,a1.x,a1.y,a1.z,a1.w};
            float bv[8] = {b0.x,b0.y,b0.z,b0.w,b1.x,b1.y,b1.z,b1.w};
#pragma unroll
            for (int i = 0; i < 8; i++)
#pragma unroll
                for (int j = 0; j < 8; j++)
                    acc[i][j] = fmaf(av[i], bv[j], acc[i][j]);
        }
        __syncthreads();
    }

#pragma unroll
    for (int i = 0; i < 8; i++){
        int m = m0 + ((i < 4) ? (ty * 4 + i) : (64 + ty * 4 + i - 4));
        if (n0 < 256){
            float4 o0 = make_float4(acc[i][0], acc[i][1], acc[i][2], acc[i][3]);
            float4 o1 = make_float4(acc[i][4], acc[i][5], acc[i][6], acc[i][7]);
            *(float4*)(g_xcraw + m * 256 + n0 + tx * 4)      = o0;
            *(float4*)(g_xcraw + m * 256 + n0 + 64 + tx * 4) = o1;
        } else {
            int nz = n0 - 256;
            float4 o0 = make_float4(silu_f(acc[i][0]), silu_f(acc[i][1]),
                                    silu_f(acc[i][2]), silu_f(acc[i][3]));
            float4 o1 = make_float4(silu_f(acc[i][4]), silu_f(acc[i][5]),
                                    silu_f(acc[i][6]), silu_f(acc[i][7]));
            *(float4*)(g_gate + m * 256 + nz + tx * 4)      = o0;
            *(float4*)(g_gate + m * 256 + nz + 64 + tx * 4) = o1;
        }
    }
}

// ---------------- K2: depthwise causal conv + bias + SiLU (register ring over L-strip) ----------------
#define LCH 16
__global__ void __launch_bounds__(256) k2_conv(const float* __restrict__ conv_w,
                                               const float* __restrict__ conv_b)
{
    int gidx = blockIdx.x * 256 + threadIdx.x;   // Bsz * (Lsz/LCH) * 64 threads
    int d4 = gidx & 63;
    int lc = (gidx >> 6) & ((Lsz / LCH) - 1);
    int b  = gidx >> (6 + 7);                    // Lsz/LCH = 128 -> 7 bits
    int d  = d4 << 2;

    float w[4][4];
#pragma unroll
    for (int q = 0; q < 4; q++){
        float4 wq = __ldg((const float4*)(conv_w + (d + q) * 4));
        w[q][0] = wq.x; w[q][1] = wq.y; w[q][2] = wq.z; w[q][3] = wq.w;
    }
    float4 bb = __ldg((const float4*)(conv_b + d));

    const int l0 = lc * LCH;
    const int bl0 = b * Lsz + l0;
    float4 zero = make_float4(0.f, 0.f, 0.f, 0.f);
    // ring: r1 = x[l-3], r2 = x[l-2], r3 = x[l-1]
    float4 r1 = (l0 >= 3) ? *(const float4*)(g_xcraw + (bl0 - 3) * 256 + d) : zero;
    float4 r2 = (l0 >= 2) ? *(const float4*)(g_xcraw + (bl0 - 2) * 256 + d) : zero;
    float4 r3 = (l0 >= 1) ? *(const float4*)(g_xcraw + (bl0 - 1) * 256 + d) : zero;

#pragma unroll
    for (int i = 0; i < LCH; i++){
        float4 cur = *(const float4*)(g_xcraw + (bl0 + i) * 256 + d);
        float a0 = bb.x, a1 = bb.y, a2 = bb.z, a3 = bb.w;
        a0 = fmaf(w[0][0], r1.x, a0); a1 = fmaf(w[1][0], r1.y, a1);
        a2 = fmaf(w[2][0], r1.z, a2); a3 = fmaf(w[3][0], r1.w, a3);
        a0 = fmaf(w[0][1], r2.x, a0); a1 = fmaf(w[1][1], r2.y, a1);
        a2 = fmaf(w[2][1], r2.z, a2); a3 = fmaf(w[3][1], r2.w, a3);
        a0 = fmaf(w[0][2], r3.x, a0); a1 = fmaf(w[1][2], r3.y, a1);
        a2 = fmaf(w[2][2], r3.z, a2); a3 = fmaf(w[3][2], r3.w, a3);
        a0 = fmaf(w[0][3], cur.x, a0); a1 = fmaf(w[1][3], cur.y, a1);
        a2 = fmaf(w[2][3], cur.z, a2); a3 = fmaf(w[3][3], cur.w, a3);
        float4 o;
        o.x = silu_f(a0); o.y = silu_f(a1); o.z = silu_f(a2); o.w = silu_f(a3);
        *(float4*)(g_xc + (bl0 + i) * 256 + d) = o;
        r1 = r2; r2 = r3; r3 = cur;
    }
}

// ---------------- K3: x_proj (40x256) + dt_proj (256x8) + softplus; emit {delta,xc}/B/C ----------------
// One warp handles 4 (b,l) positions; x_proj_w staged in shared memory.
__global__ void __launch_bounds__(256) k3_xproj(const float* __restrict__ xpw,
                                                const float* __restrict__ dtw,
                                                const float* __restrict__ dtb)
{
    __shared__ __align__(16) float sw[40 * 256];
    __shared__ float sdbc[8][4][40];
    const int tid  = threadIdx.x;
    const int lane = tid & 31;
    const int wp   = tid >> 5;
    const int bl0  = (blockIdx.x * 8 + wp) * 4;

#pragma unroll
    for (int i = 0; i < 10; i++)
        ((float4*)sw)[i * 256 + tid] = ((const float4*)xpw)[i * 256 + tid];
    __syncthreads();

    float xcl[4][8];
#pragma unroll
    for (int p = 0; p < 4; p++)
#pragma unroll
        for (int k = 0; k < 8; k++)
            xcl[p][k] = g_xc[(bl0 + p) * 256 + k * 32 + lane];

#pragma unroll 8
    for (int j = 0; j < 40; j++){
        float wl[8];
#pragma unroll
        for (int k = 0; k < 8; k++) wl[k] = sw[j * 256 + k * 32 + lane];
        float s0 = 0.f, s1 = 0.f, s2 = 0.f, s3 = 0.f;
#pragma unroll
        for (int k = 0; k < 8; k++){
            s0 = fmaf(wl[k], xcl[0][k], s0);
            s1 = fmaf(wl[k], xcl[1][k], s1);
            s2 = fmaf(wl[k], xcl[2][k], s2);
            s3 = fmaf(wl[k], xcl[3][k], s3);
        }
#pragma unroll
        for (int off = 16; off; off >>= 1){
            s0 += __shfl_xor_sync(0xffffffffu, s0, off);
            s1 += __shfl_xor_sync(0xffffffffu, s1, off);
            s2 += __shfl_xor_sync(0xffffffffu, s2, off);
            s3 += __shfl_xor_sync(0xffffffffu, s3, off);
        }
        if (lane == 0){
            sdbc[wp][0][j] = s0; sdbc[wp][1][j] = s1;
            sdbc[wp][2][j] = s2; sdbc[wp][3][j] = s3;
        }
    }
    __syncwarp();

    if (lane < 16){
#pragma unroll
        for (int p = 0; p < 4; p++){
            g_Bm[(bl0 + p) * 16 + lane] = sdbc[wp][p][8  + lane];
            g_Cm[(bl0 + p) * 16 + lane] = sdbc[wp][p][24 + lane];
        }
    }

#pragma unroll
    for (int k = 0; k < 8; k++){
        int d = k * 32 + lane;
        float4 w0 = __ldg((const float4*)(dtw + d * 8));
        float4 w1 = __ldg((const float4*)(dtw + d * 8 + 4));
        float bias = __ldg(dtb + d);
#pragma unroll
        for (int p = 0; p < 4; p++){
            const float* dv = sdbc[wp][p];
            float t = bias;
            t = fmaf(w0.x, dv[0], t); t = fmaf(w0.y, dv[1], t);
            t = fmaf(w0.z, dv[2], t); t = fmaf(w0.w, dv[3], t);
            t = fmaf(w1.x, dv[4], t); t = fmaf(w1.y, dv[5], t);
            t = fmaf(w1.z, dv[6], t); t = fmaf(w1.w, dv[7], t);
            g_dxc[(bl0 + p) * 256 + d] = make_float2(softplus_f(t), xcl[p][k]);
        }
    }
}

// ---------------- K4: chunked selective scan, pass A (4-step software prefetch) ----------------
// dA_n = e1^(n+1) with e1 = exp(delta*A[d,0]); ratio structure verified at runtime.
// Per step: LDG.64 {delta,xc} + LDG.32 gate.
__global__ void __launch_bounds__(256, 2) k4_scan(const float* __restrict__ A_log,
                                                  const float* __restrict__ Dvec)
{
    __shared__ __align__(16) float sB[CLEN * 16];
    __shared__ __align__(16) float sC[CLEN * 16];

    const int b = blockIdx.x >> 5;       // NCH = 32
    const int c = blockIdx.x & 31;
    const int d = threadIdx.x;

    const float An0 = -__expf(__ldg(A_log + d * 16));
    bool pw_ok = true;
#pragma unroll
    for (int n = 1; n < 16; n++){
        float Ann = -__expf(__ldg(A_log + d * 16 + n));
        pw_ok = pw_ok && (fabsf(Ann / An0 - (float)(n + 1)) < 1e-3f);
    }
    const float Dd = __ldg(Dvec + d);

    const int l0 = b * Lsz + c * CLEN;
    {
        const float4* gB = (const float4*)(g_Bm + l0 * 16);
        const float4* gC = (const float4*)(g_Cm + l0 * 16);
        ((float4*)sB)[d] = gB[d];
        ((float4*)sC)[d] = gC[d];
    }
    __syncthreads();

    float h[16], P[16], S[16];
#pragma unroll
    for (int n = 0; n < 16; n++){ h[n] = 0.0f; P[n] = 1.0f; S[n] = 0.0f; }
    float accl = 0.0f;

    int base = l0 * 256 + d;

    if (pw_ok){
        // prefetch 4 steps ahead
        float2 pdx[4]; float pg[4];
#pragma unroll
        for (int q = 0; q < 4; q++){
            pdx[q] = g_dxc[base + q * 256];
            pg[q]  = __ldg(g_gate + base + q * 256);
        }
#pragma unroll 1
        for (int t = 0; t < CLEN; t += 4){
            float2 cdx[4]; float cg[4];
#pragma unroll
            for (int q = 0; q < 4; q++){ cdx[q] = pdx[q]; cg[q] = pg[q]; }
            int nb = base + 4 * 256;
            if (t + 4 < CLEN){
#pragma unroll
                for (int q = 0; q < 4; q++){
                    pdx[q] = g_dxc[nb + q * 256];
                    pg[q]  = __ldg(g_gate + nb + q * 256);
                }
            }
            float e1v[4];
#pragma unroll
            for (int q = 0; q < 4; q++) e1v[q] = __expf(cdx[q].x * An0);

#pragma unroll
            for (int q = 0; q < 4; q++){
                float gv  = cg[q];
                float xcv = cdx[q].y;
                float dxv = cdx[q].x * xcv;

                float Bv[16], Cv[16];
#pragma unroll
                for (int r = 0; r < 4; r++){
                    float4 bbv = ((const float4*)sB)[(t + q) * 4 + r];
                    float4 ccv = ((const float4*)sC)[(t + q) * 4 + r];
                    Bv[r*4+0] = bbv.x; Bv[r*4+1] = bbv.y; Bv[r*4+2] = bbv.z; Bv[r*4+3] = bbv.w;
                    Cv[r*4+0] = ccv.x; Cv[r*4+1] = ccv.y; Cv[r*4+2] = ccv.z; Cv[r*4+3] = ccv.w;
                }

                float p[16];
                p[0] = e1v[q];
#pragma unroll
                for (int i = 1; i < 16; i++) p[i] = p[(i - 1) >> 1] * p[i >> 1];

                float yloc = 0.0f;
#pragma unroll
                for (int n = 0; n < 16; n++){
                    P[n] *= p[n];
                    h[n] = fmaf(p[n], h[n], dxv * Bv[n]);
                    yloc = fmaf(h[n], Cv[n], yloc);
                    S[n] = fmaf(P[n], gv * Cv[n], S[n]);
                }
                accl = fmaf(gv, fmaf(xcv, Dd, yloc), accl);
            }
            base = nb;
        }
    } else {
        // cold generic path (correctness only)
#pragma unroll 1
        for (int t = 0; t < CLEN; t++){
            float2 dxc  = g_dxc[base];
            float delta = dxc.x;
            float gv    = g_gate[base];
            float xcv   = dxc.y;
            float dxv   = delta * xcv;
            float yloc  = 0.0f;
#pragma unroll 4
            for (int n = 0; n < 16; n++){
                float An = -__expf(__ldg(A_log + d * 16 + n));
                float dA = __expf(delta * An);
                float Bn = sB[t * 16 + n];
                float Cn = sC[t * 16 + n];
                P[n] *= dA;
                h[n] = fmaf(dA, h[n], dxv * Bn);
                yloc = fmaf(h[n], Cn, yloc);
                S[n] = fmaf(P[n], gv * Cn, S[n]);
            }
            accl = fmaf(gv, fmaf(xcv, Dd, yloc), accl);
            base += 256;
        }
    }

    const int ob = (b * 256 + d) * NCH + c;
    g_accl[ob] = accl;
#pragma unroll
    for (int n = 0; n < 16; n++){
        g_P [ob * 16 + n] = P[n];
        g_hl[ob * 16 + n] = h[n];
        g_S [ob * 16 + n] = S[n];
    }
}

// ---------------- K5: chunk combine (sequential over 32 chunks per (b,d)) ----------------
__global__ void __launch_bounds__(256) k5_combine()
{
    int gid = blockIdx.x * 256 + threadIdx.x;   // (b,d): 0..4095
    float h[16];
#pragma unroll
    for (int n = 0; n < 16; n++) h[n] = 0.0f;
    float acc = 0.0f;
#pragma unroll 1
    for (int c = 0; c < NCH; c++){
        int base = gid * NCH + c;
        acc += g_accl[base];
        const float4* sp = (const float4*)(g_S  + base * 16);
        const float4* pp = (const float4*)(g_P  + base * 16);
        const float4* hp = (const float4*)(g_hl + base * 16);
#pragma unroll
        for (int q = 0; q < 4; q++){
            float4 sv = sp[q], pv = pp[q], hv = hp[q];
            acc = fmaf(h[q*4+0], sv.x, acc);
            acc = fmaf(h[q*4+1], sv.y, acc);
            acc = fmaf(h[q*4+2], sv.z, acc);
            acc = fmaf(h[q*4+3], sv.w, acc);
            h[q*4+0] = fmaf(pv.x, h[q*4+0], hv.x);
            h[q*4+1] = fmaf(pv.y, h[q*4+1], hv.y);
            h[q*4+2] = fmaf(pv.z, h[q*4+2], hv.z);
            h[q*4+3] = fmaf(pv.w, h[q*4+3], hv.w);
        }
    }
    g_acc[gid] = acc;
}

// ---------------- K6: out_proj + mean + classifier ----------------
__global__ void __launch_bounds__(128) k6_head(const float* __restrict__ opw,
                                               const float* __restrict__ clw,
                                               const float* __restrict__ clb,
                                               float* __restrict__ out)
{
    __shared__ float mvec[128];
    int b = blockIdx.x, j = threadIdx.x;
    float s = 0.0f;
    const float* ar = g_acc + b * 256;
#pragma unroll 8
    for (int e = 0; e < 256; e++) s = fmaf(ar[e], __ldg(opw + j * 256 + e), s);
    mvec[j] = s * (1.0f / 2048.0f);
    __syncthreads();
    if (j < 2){
        float t = __ldg(clb + j);
#pragma unroll 8
        for (int e = 0; e < 128; e++) t = fmaf(mvec[e], __ldg(clw + j * 128 + e), t);
        out[b * 2 + j] = t;
    }
}

// ---------------- launch ----------------
extern "C" void kernel_launch(void* const* d_in, const int* in_sizes, int n_in,
                              void* d_out, int out_size)
{
    const int*   ids  = (const int*)  d_in[0];
    const float* emb  = (const float*)d_in[1];
    const float* ipw  = (const float*)d_in[2];
    const float* cw   = (const float*)d_in[3];
    const float* cb   = (const float*)d_in[4];
    const float* xpw  = (const float*)d_in[5];
    const float* dtw  = (const float*)d_in[6];
    const float* dtb  = (const float*)d_in[7];
    const float* alog = (const float*)d_in[8];
    const float* dvec = (const float*)d_in[9];
    const float* opw  = (const float*)d_in[10];
    const float* clw  = (const float*)d_in[11];
    const float* clb  = (const float*)d_in[12];
    float* out = (float*)d_out;

    dim3 g1(BLn / 128, 4);
    k1_inproj<<<g1, 256>>>(ids, emb, ipw);
    k2_conv<<<(Bsz * (Lsz / LCH) * 64) / 256, 256>>>(cw, cb);
    k3_xproj<<<BLn / 32, 256>>>(xpw, dtw, dtb);
    k4_scan<<<Bsz * NCH, 256>>>(alog, dvec);
    k5_combine<<<(Bsz * DI) / 256, 256>>>();
    k6_head<<<Bsz, 128>>>(opw, clw, clb, out);
}

// round 5
// speedup vs baseline: 1.4289x; 1.1858x over previous
#include <cuda_runtime.h>
#include <math.h>
#include <stdint.h>

// Problem constants
#define Bsz 16
#define Lsz 2048
#define BLn (Bsz*Lsz)          // 32768 (b,l) positions
#define DI 256                 // d_inner
#define DS 16                  // d_state
#define NCH 32                 // scan chunks
#define CLEN (Lsz/NCH)         // 64 steps per chunk

// ---------------- scratch (static device globals; no allocation) ----------------
static __device__ float  g_xcraw[BLn*DI];   // in_proj x-half (pre conv)
static __device__ float  g_gate [BLn*DI];   // silu(z)
static __device__ float  g_xc   [BLn*DI];   // silu(conv(x))
static __device__ float2 g_dxc  [BLn*DI];   // packed {delta, xc} from K3
static __device__ float  g_Bm   [BLn*DS];
static __device__ float  g_Cm   [BLn*DS];
static __device__ float  g_P    [Bsz*DI*NCH*DS];  // chunk cum-prod of dA
static __device__ float  g_hl   [Bsz*DI*NCH*DS];  // chunk-local h (h_in = 0)
static __device__ float  g_S    [Bsz*DI*NCH*DS];  // sum_t g*C*cumA
static __device__ float  g_accl [Bsz*DI*NCH];     // chunk-local gated y accum
static __device__ float  g_acc  [Bsz*DI];         // final per-channel sums

__device__ __forceinline__ float silu_f(float x){ return x / (1.0f + __expf(-x)); }
__device__ __forceinline__ float softplus_f(float x){ return (x > 20.0f) ? x : log1pf(__expf(x)); }
__device__ __forceinline__ float to_tf32(float x){
    uint32_t u; asm("cvt.rna.tf32.f32 %0, %1;" : "=r"(u) : "f"(x));
    return __uint_as_float(u);
}

// ---------------- K1: embedding gather + in_proj GEMM via tf32 mma.sync ----------------
// out[m,n] = sum_k emb[ids[m],k] * W[n,k];  M=32768, N=512, K=128.
// Block 256 thr (8 warps), tile BM=128 x BN=64, two K-passes of 64.
// smem holds fragment-permuted tf32 operands: A [m16][k8][lane][4], B [n8][k8][lane][2].
__global__ void __launch_bounds__(256) k1_inproj(const int* __restrict__ ids,
                                                 const float* __restrict__ emb,
                                                 const float* __restrict__ wproj)
{
    __shared__ __align__(16) float sA[8*8*32*4];   // 32 KB
    __shared__ __align__(16) float sW[8*8*32*2];   // 16 KB
    const int tid   = threadIdx.x;
    const int lane  = tid & 31;
    const int w     = tid >> 5;
    const int warpM = w >> 1;       // 0..3  (32 rows each)
    const int warpN = w & 1;        // 0..1  (32 cols each)
    const int m0 = blockIdx.x * 128;
    const int n0 = blockIdx.y * 64;

    int rid[8];
#pragma unroll
    for (int i = 0; i < 8; i++) rid[i] = ids[m0 + i * 16 + (tid >> 4)];

    float acc[2][4][4];
#pragma unroll
    for (int mt = 0; mt < 2; mt++)
#pragma unroll
        for (int nt = 0; nt < 4; nt++)
#pragma unroll
            for (int r = 0; r < 4; r++) acc[mt][nt][r] = 0.0f;

#pragma unroll 1
    for (int pass = 0; pass < 2; pass++){
        const int k0 = pass * 64;

        // ---- fill A: 128 rows x 64 k (tf32), fragment-permuted ----
        {
            const int kq4 = tid & 15;            // which float4 within the 64-k row
#pragma unroll
            for (int i = 0; i < 8; i++){
                int row = i * 16 + (tid >> 4);
                float4 v = *(const float4*)(emb + rid[i] * 128 + k0 + kq4 * 4);
                int base = (((row >> 4) * 8 + (kq4 >> 1)) * 32 + (row & 7) * 4) * 4
                           + ((row >> 3) & 1) + 2 * (kq4 & 1);
                sA[base + 0*4] = to_tf32(v.x);
                sA[base + 1*4] = to_tf32(v.y);
                sA[base + 2*4] = to_tf32(v.z);
                sA[base + 3*4] = to_tf32(v.w);
            }
        }
        // ---- fill W: 64 rows x 64 k (tf32), fragment-permuted ----
        {
#pragma unroll
            for (int i = 0; i < 4; i++){
                int idx = i * 256 + tid;         // 0..1023
                int n   = idx >> 4;              // 0..63
                int kq4 = idx & 15;
                float4 v = *(const float4*)(wproj + (n0 + n) * 128 + k0 + kq4 * 4);
                int base = (((n >> 3) * 8 + (kq4 >> 1)) * 32 + (n & 7) * 4) * 2 + (kq4 & 1);
                sW[base + 0*2] = to_tf32(v.x);
                sW[base + 1*2] = to_tf32(v.y);
                sW[base + 2*2] = to_tf32(v.z);
                sW[base + 3*2] = to_tf32(v.w);
            }
        }
        __syncthreads();

#pragma unroll
        for (int k8 = 0; k8 < 8; k8++){
            float4 af[2];
#pragma unroll
            for (int mt = 0; mt < 2; mt++)
                af[mt] = *(const float4*)&sA[(((warpM * 2 + mt) * 8 + k8) * 32 + lane) * 4];
            float2 bf[4];
#pragma unroll
            for (int nt = 0; nt < 4; nt++)
                bf[nt] = *(const float2*)&sW[(((warpN * 4 + nt) * 8 + k8) * 32 + lane) * 2];
#pragma unroll
            for (int mt = 0; mt < 2; mt++)
#pragma unroll
                for (int nt = 0; nt < 4; nt++){
                    asm volatile(
                        "mma.sync.aligned.m16n8k8.row.col.f32.tf32.tf32.f32 "
                        "{%0,%1,%2,%3},{%4,%5,%6,%7},{%8,%9},{%0,%1,%2,%3};"
                        : "+f"(acc[mt][nt][0]), "+f"(acc[mt][nt][1]),
                          "+f"(acc[mt][nt][2]), "+f"(acc[mt][nt][3])
                        : "r"(__float_as_uint(af[mt].x)), "r"(__float_as_uint(af[mt].y)),
                          "r"(__float_as_uint(af[mt].z)), "r"(__float_as_uint(af[mt].w)),
                          "r"(__float_as_uint(bf[nt].x)), "r"(__float_as_uint(bf[nt].y)));
                }
        }
        __syncthreads();
    }

    // ---- epilogue: scatter accumulators; SiLU on z half ----
#pragma unroll
    for (int mt = 0; mt < 2; mt++)
#pragma unroll
        for (int nt = 0; nt < 4; nt++)
#pragma unroll
            for (int rh = 0; rh < 2; rh++){
                int m = m0 + warpM * 32 + mt * 16 + (lane >> 2) + rh * 8;
                int n = n0 + warpN * 32 + nt * 8 + (lane & 3) * 2;
                float v0 = acc[mt][nt][rh * 2 + 0];
                float v1 = acc[mt][nt][rh * 2 + 1];
                if (n0 < 256){
                    *(float2*)(g_xcraw + m * 256 + n) = make_float2(v0, v1);
                } else {
                    *(float2*)(g_gate + m * 256 + (n - 256)) =
                        make_float2(silu_f(v0), silu_f(v1));
                }
            }
}

// ---------------- K2: depthwise causal conv + bias + SiLU (register ring over L-strip) ----------------
#define LCH 16
__global__ void __launch_bounds__(256) k2_conv(const float* __restrict__ conv_w,
                                               const float* __restrict__ conv_b)
{
    int gidx = blockIdx.x * 256 + threadIdx.x;   // Bsz * (Lsz/LCH) * 64 threads
    int d4 = gidx & 63;
    int lc = (gidx >> 6) & ((Lsz / LCH) - 1);
    int b  = gidx >> (6 + 7);                    // Lsz/LCH = 128 -> 7 bits
    int d  = d4 << 2;

    float w[4][4];
#pragma unroll
    for (int q = 0; q < 4; q++){
        float4 wq = __ldg((const float4*)(conv_w + (d + q) * 4));
        w[q][0] = wq.x; w[q][1] = wq.y; w[q][2] = wq.z; w[q][3] = wq.w;
    }
    float4 bb = __ldg((const float4*)(conv_b + d));

    const int l0 = lc * LCH;
    const int bl0 = b * Lsz + l0;
    float4 zero = make_float4(0.f, 0.f, 0.f, 0.f);
    float4 r1 = (l0 >= 3) ? *(const float4*)(g_xcraw + (bl0 - 3) * 256 + d) : zero;
    float4 r2 = (l0 >= 2) ? *(const float4*)(g_xcraw + (bl0 - 2) * 256 + d) : zero;
    float4 r3 = (l0 >= 1) ? *(const float4*)(g_xcraw + (bl0 - 1) * 256 + d) : zero;

#pragma unroll
    for (int i = 0; i < LCH; i++){
        float4 cur = *(const float4*)(g_xcraw + (bl0 + i) * 256 + d);
        float a0 = bb.x, a1 = bb.y, a2 = bb.z, a3 = bb.w;
        a0 = fmaf(w[0][0], r1.x, a0); a1 = fmaf(w[1][0], r1.y, a1);
        a2 = fmaf(w[2][0], r1.z, a2); a3 = fmaf(w[3][0], r1.w, a3);
        a0 = fmaf(w[0][1], r2.x, a0); a1 = fmaf(w[1][1], r2.y, a1);
        a2 = fmaf(w[2][1], r2.z, a2); a3 = fmaf(w[3][1], r2.w, a3);
        a0 = fmaf(w[0][2], r3.x, a0); a1 = fmaf(w[1][2], r3.y, a1);
        a2 = fmaf(w[2][2], r3.z, a2); a3 = fmaf(w[3][2], r3.w, a3);
        a0 = fmaf(w[0][3], cur.x, a0); a1 = fmaf(w[1][3], cur.y, a1);
        a2 = fmaf(w[2][3], cur.z, a2); a3 = fmaf(w[3][3], cur.w, a3);
        float4 o;
        o.x = silu_f(a0); o.y = silu_f(a1); o.z = silu_f(a2); o.w = silu_f(a3);
        *(float4*)(g_xc + (bl0 + i) * 256 + d) = o;
        r1 = r2; r2 = r3; r3 = cur;
    }
}

// ---------------- K3: x_proj (40x256) + dt_proj (256x8) + softplus; emit {delta,xc}/B/C ----------------
__global__ void __launch_bounds__(256) k3_xproj(const float* __restrict__ xpw,
                                                const float* __restrict__ dtw,
                                                const float* __restrict__ dtb)
{
    __shared__ __align__(16) float sw[40 * 256];
    __shared__ float sdbc[8][4][40];
    const int tid  = threadIdx.x;
    const int lane = tid & 31;
    const int wp   = tid >> 5;
    const int bl0  = (blockIdx.x * 8 + wp) * 4;

#pragma unroll
    for (int i = 0; i < 10; i++)
        ((float4*)sw)[i * 256 + tid] = ((const float4*)xpw)[i * 256 + tid];
    __syncthreads();

    float xcl[4][8];
#pragma unroll
    for (int p = 0; p < 4; p++)
#pragma unroll
        for (int k = 0; k < 8; k++)
            xcl[p][k] = g_xc[(bl0 + p) * 256 + k * 32 + lane];

#pragma unroll 8
    for (int j = 0; j < 40; j++){
        float wl[8];
#pragma unroll
        for (int k = 0; k < 8; k++) wl[k] = sw[j * 256 + k * 32 + lane];
        float s0 = 0.f, s1 = 0.f, s2 = 0.f, s3 = 0.f;
#pragma unroll
        for (int k = 0; k < 8; k++){
            s0 = fmaf(wl[k], xcl[0][k], s0);
            s1 = fmaf(wl[k], xcl[1][k], s1);
            s2 = fmaf(wl[k], xcl[2][k], s2);
            s3 = fmaf(wl[k], xcl[3][k], s3);
        }
#pragma unroll
        for (int off = 16; off; off >>= 1){
            s0 += __shfl_xor_sync(0xffffffffu, s0, off);
            s1 += __shfl_xor_sync(0xffffffffu, s1, off);
            s2 += __shfl_xor_sync(0xffffffffu, s2, off);
            s3 += __shfl_xor_sync(0xffffffffu, s3, off);
        }
        if (lane == 0){
            sdbc[wp][0][j] = s0; sdbc[wp][1][j] = s1;
            sdbc[wp][2][j] = s2; sdbc[wp][3][j] = s3;
        }
    }
    __syncwarp();

    if (lane < 16){
#pragma unroll
        for (int p = 0; p < 4; p++){
            g_Bm[(bl0 + p) * 16 + lane] = sdbc[wp][p][8  + lane];
            g_Cm[(bl0 + p) * 16 + lane] = sdbc[wp][p][24 + lane];
        }
    }

#pragma unroll
    for (int k = 0; k < 8; k++){
        int d = k * 32 + lane;
        float4 w0 = __ldg((const float4*)(dtw + d * 8));
        float4 w1 = __ldg((const float4*)(dtw + d * 8 + 4));
        float bias = __ldg(dtb + d);
#pragma unroll
        for (int p = 0; p < 4; p++){
            const float* dv = sdbc[wp][p];
            float t = bias;
            t = fmaf(w0.x, dv[0], t); t = fmaf(w0.y, dv[1], t);
            t = fmaf(w0.z, dv[2], t); t = fmaf(w0.w, dv[3], t);
            t = fmaf(w1.x, dv[4], t); t = fmaf(w1.y, dv[5], t);
            t = fmaf(w1.z, dv[6], t); t = fmaf(w1.w, dv[7], t);
            g_dxc[(bl0 + p) * 256 + d] = make_float2(softplus_f(t), xcl[p][k]);
        }
    }
}

// ---------------- K4: chunked selective scan, pass A (split-state: 2 threads/channel) ----------------
// Block covers 128 channels x 2 state-halves. dA_n = e1^(n+1), e1 = exp(delta*A[d,0]);
// half 1 multiplies the e1^1..e1^8 tree by e1^8. One shfl per step for the y reduction.
__global__ void __launch_bounds__(256, 3) k4_scan(const float* __restrict__ A_log,
                                                  const float* __restrict__ Dvec)
{
    __shared__ __align__(16) float sB[CLEN * 16];
    __shared__ __align__(16) float sC[CLEN * 16];

    const int b   = blockIdx.x >> 6;         // 32 chunks * 2 channel-halves
    const int c   = (blockIdx.x >> 1) & 31;
    const int hb  = blockIdx.x & 1;          // channel-half block
    const int tid = threadIdx.x;
    const int dl  = tid >> 1;                // 0..127
    const int sh  = tid & 1;                 // state half
    const int d   = hb * 128 + dl;
    const int n0  = sh * 8;

    const float An0 = -__expf(__ldg(A_log + d * 16));
    bool pw_ok = true;
#pragma unroll
    for (int j = 0; j < 8; j++){
        float Ann = -__expf(__ldg(A_log + d * 16 + n0 + j));
        pw_ok = pw_ok && (fabsf(Ann / An0 - (float)(n0 + j + 1)) < 1e-3f);
    }
    const float Dd = __ldg(Dvec + d);

    const int l0 = b * Lsz + c * CLEN;
    {
        const float4* gB = (const float4*)(g_Bm + l0 * 16);
        const float4* gC = (const float4*)(g_Cm + l0 * 16);
        ((float4*)sB)[tid] = gB[tid];
        ((float4*)sC)[tid] = gC[tid];
    }
    __syncthreads();

    float h[8], P[8], S[8];
#pragma unroll
    for (int j = 0; j < 8; j++){ h[j] = 0.0f; P[j] = 1.0f; S[j] = 0.0f; }
    float accl = 0.0f;

    int base = l0 * 256 + d;

    if (pw_ok){
        float2 pdx[4]; float pg[4];
#pragma unroll
        for (int q = 0; q < 4; q++){
            pdx[q] = g_dxc[base + q * 256];
            pg[q]  = __ldg(g_gate + base + q * 256);
        }
#pragma unroll 1
        for (int t = 0; t < CLEN; t += 4){
            float2 cdx[4]; float cg[4];
#pragma unroll
            for (int q = 0; q < 4; q++){ cdx[q] = pdx[q]; cg[q] = pg[q]; }
            int nb = base + 4 * 256;
            if (t + 4 < CLEN){
#pragma unroll
                for (int q = 0; q < 4; q++){
                    pdx[q] = g_dxc[nb + q * 256];
                    pg[q]  = __ldg(g_gate + nb + q * 256);
                }
            }
            float e1v[4];
#pragma unroll
            for (int q = 0; q < 4; q++) e1v[q] = __expf(cdx[q].x * An0);

#pragma unroll
            for (int q = 0; q < 4; q++){
                float gv  = cg[q];
                float xcv = cdx[q].y;
                float dxv = cdx[q].x * xcv;

                // powers e1^1..e1^8, then shift by e1^8 for the upper half
                float qp[8];
                qp[0] = e1v[q];
#pragma unroll
                for (int i = 1; i < 8; i++) qp[i] = qp[(i - 1) >> 1] * qp[i >> 1];
                float fac = sh ? qp[7] : 1.0f;

                float4 bb0 = ((const float4*)sB)[(t + q) * 4 + sh * 2 + 0];
                float4 bb1 = ((const float4*)sB)[(t + q) * 4 + sh * 2 + 1];
                float4 cc0 = ((const float4*)sC)[(t + q) * 4 + sh * 2 + 0];
                float4 cc1 = ((const float4*)sC)[(t + q) * 4 + sh * 2 + 1];
                float Bv[8] = {bb0.x, bb0.y, bb0.z, bb0.w, bb1.x, bb1.y, bb1.z, bb1.w};
                float Cv[8] = {cc0.x, cc0.y, cc0.z, cc0.w, cc1.x, cc1.y, cc1.z, cc1.w};

                float yloc = 0.0f;
#pragma unroll
                for (int j = 0; j < 8; j++){
                    float pj = qp[j] * fac;
                    P[j] *= pj;
                    h[j] = fmaf(pj, h[j], dxv * Bv[j]);
                    yloc = fmaf(h[j], Cv[j], yloc);
                    S[j] = fmaf(P[j], gv * Cv[j], S[j]);
                }
                yloc += __shfl_xor_sync(0xffffffffu, yloc, 1);
                accl = fmaf(gv, fmaf(xcv, Dd, yloc), accl);
            }
            base = nb;
        }
    } else {
        // cold generic path (correctness only)
#pragma unroll 1
        for (int t = 0; t < CLEN; t++){
            float2 dxc  = g_dxc[base];
            float delta = dxc.x;
            float gv    = g_gate[base];
            float xcv   = dxc.y;
            float dxv   = delta * xcv;
            float yloc  = 0.0f;
#pragma unroll 4
            for (int j = 0; j < 8; j++){
                float An = -__expf(__ldg(A_log + d * 16 + n0 + j));
                float dA = __expf(delta * An);
                float Bn = sB[t * 16 + n0 + j];
                float Cn = sC[t * 16 + n0 + j];
                P[j] *= dA;
                h[j] = fmaf(dA, h[j], dxv * Bn);
                yloc = fmaf(h[j], Cn, yloc);
                S[j] = fmaf(P[j], gv * Cn, S[j]);
            }
            yloc += __shfl_xor_sync(0xffffffffu, yloc, 1);
            accl = fmaf(gv, fmaf(xcv, Dd, yloc), accl);
            base += 256;
        }
    }

    const int ob = (b * 256 + d) * NCH + c;
    if (sh == 0) g_accl[ob] = accl;
    *(float4*)(g_P  + ob * 16 + n0)     = make_float4(P[0], P[1], P[2], P[3]);
    *(float4*)(g_P  + ob * 16 + n0 + 4) = make_float4(P[4], P[5], P[6], P[7]);
    *(float4*)(g_hl + ob * 16 + n0)     = make_float4(h[0], h[1], h[2], h[3]);
    *(float4*)(g_hl + ob * 16 + n0 + 4) = make_float4(h[4], h[5], h[6], h[7]);
    *(float4*)(g_S  + ob * 16 + n0)     = make_float4(S[0], S[1], S[2], S[3]);
    *(float4*)(g_S  + ob * 16 + n0 + 4) = make_float4(S[4], S[5], S[6], S[7]);
}

// ---------------- K5: chunk combine (sequential over 32 chunks per (b,d)) ----------------
__global__ void __launch_bounds__(256) k5_combine()
{
    int gid = blockIdx.x * 256 + threadIdx.x;   // (b,d): 0..4095
    float h[16];
#pragma unroll
    for (int n = 0; n < 16; n++) h[n] = 0.0f;
    float acc = 0.0f;
#pragma unroll 1
    for (int c = 0; c < NCH; c++){
        int base = gid * NCH + c;
        acc += g_accl[base];
        const float4* sp = (const float4*)(g_S  + base * 16);
        const float4* pp = (const float4*)(g_P  + base * 16);
        const float4* hp = (const float4*)(g_hl + base * 16);
#pragma unroll
        for (int q = 0; q < 4; q++){
            float4 sv = sp[q], pv = pp[q], hv = hp[q];
            acc = fmaf(h[q*4+0], sv.x, acc);
            acc = fmaf(h[q*4+1], sv.y, acc);
            acc = fmaf(h[q*4+2], sv.z, acc);
            acc = fmaf(h[q*4+3], sv.w, acc);
            h[q*4+0] = fmaf(pv.x, h[q*4+0], hv.x);
            h[q*4+1] = fmaf(pv.y, h[q*4+1], hv.y);
            h[q*4+2] = fmaf(pv.z, h[q*4+2], hv.z);
            h[q*4+3] = fmaf(pv.w, h[q*4+3], hv.w);
        }
    }
    g_acc[gid] = acc;
}

// ---------------- K6: out_proj + mean + classifier ----------------
__global__ void __launch_bounds__(128) k6_head(const float* __restrict__ opw,
                                               const float* __restrict__ clw,
                                               const float* __restrict__ clb,
                                               float* __restrict__ out)
{
    __shared__ float mvec[128];
    int b = blockIdx.x, j = threadIdx.x;
    float s = 0.0f;
    const float* ar = g_acc + b * 256;
#pragma unroll 8
    for (int e = 0; e < 256; e++) s = fmaf(ar[e], __ldg(opw + j * 256 + e), s);
    mvec[j] = s * (1.0f / 2048.0f);
    __syncthreads();
    if (j < 2){
        float t = __ldg(clb + j);
#pragma unroll 8
        for (int e = 0; e < 128; e++) t = fmaf(mvec[e], __ldg(clw + j * 128 + e), t);
        out[b * 2 + j] = t;
    }
}

// ---------------- launch ----------------
extern "C" void kernel_launch(void* const* d_in, const int* in_sizes, int n_in,
                              void* d_out, int out_size)
{
    const int*   ids  = (const int*)  d_in[0];
    const float* emb  = (const float*)d_in[1];
    const float* ipw  = (const float*)d_in[2];
    const float* cw   = (const float*)d_in[3];
    const float* cb   = (const float*)d_in[4];
    const float* xpw  = (const float*)d_in[5];
    const float* dtw  = (const float*)d_in[6];
    const float* dtb  = (const float*)d_in[7];
    const float* alog = (const float*)d_in[8];
    const float* dvec = (const float*)d_in[9];
    const float* opw  = (const float*)d_in[10];
    const float* clw  = (const float*)d_in[11];
    const float* clb  = (const float*)d_in[12];
    float* out = (float*)d_out;

    dim3 g1(BLn / 128, 8);   // 256 m-tiles x 8 n-tiles of 64
    k1_inproj<<<g1, 256>>>(ids, emb, ipw);
    k2_conv<<<(Bsz * (Lsz / LCH) * 64) / 256, 256>>>(cw, cb);
    k3_xproj<<<BLn / 32, 256>>>(xpw, dtw, dtb);
    k4_scan<<<Bsz * NCH * 2, 256>>>(alog, dvec);
    k5_combine<<<(Bsz * DI) / 256, 256>>>();
    k6_head<<<Bsz, 128>>>(opw, clw, clb, out);
}

// round 6
// speedup vs baseline: 1.4829x; 1.0378x over previous
#include <cuda_runtime.h>
#include <math.h>
#include <stdint.h>

// Problem constants
#define Bsz 16
#define Lsz 2048
#define BLn (Bsz*Lsz)          // 32768 (b,l) positions
#define DI 256                 // d_inner
#define DS 16                  // d_state
#define NCH 32                 // scan chunks
#define CLEN (Lsz/NCH)         // 64 steps per chunk

// ---------------- scratch (static device globals; no allocation) ----------------
static __device__ float  g_xcraw[BLn*DI];   // in_proj x-half (pre conv)
static __device__ float  g_gate [BLn*DI];   // silu(z)
static __device__ float  g_xc   [BLn*DI];   // silu(conv(x))
static __device__ float2 g_dxc  [BLn*DI];   // packed {delta, xc} from K3
static __device__ float  g_Bm   [BLn*DS];
static __device__ float  g_Cm   [BLn*DS];
static __device__ float  g_P    [Bsz*DI*NCH*DS];  // chunk cum-prod of dA
static __device__ float  g_hl   [Bsz*DI*NCH*DS];  // chunk-local h (h_in = 0)
static __device__ float  g_S    [Bsz*DI*NCH*DS];  // sum_t g*C*cumA
static __device__ float  g_accl [Bsz*DI*NCH];     // chunk-local gated y accum
static __device__ float  g_acc  [Bsz*DI];         // final per-channel sums

__device__ __forceinline__ float silu_f(float x){ return x / (1.0f + __expf(-x)); }
__device__ __forceinline__ float softplus_f(float x){ return (x > 20.0f) ? x : log1pf(__expf(x)); }
__device__ __forceinline__ float to_tf32(float x){
    uint32_t u; asm("cvt.rna.tf32.f32 %0, %1;" : "=r"(u) : "f"(x));
    return __uint_as_float(u);
}

// ---------------- K1: embedding gather + in_proj GEMM via tf32 mma.sync ----------------
// out[m,n] = sum_k emb[ids[m],k] * W[n,k];  M=32768, N=512, K=128.
// Block 256 thr (8 warps), tile BM=128 x BN=64, two K-passes of 64.
// smem (48KB union): operands fragment-permuted; reused as epilogue staging tile.
__global__ void __launch_bounds__(256) k1_inproj(const int* __restrict__ ids,
                                                 const float* __restrict__ emb,
                                                 const float* __restrict__ wproj)
{
    __shared__ __align__(16) float smem_all[12288];   // 48 KB
    float* sA = smem_all;           // 8*8*32*4 = 8192 floats (32 KB)
    float* sW = smem_all + 8192;    // 8*8*32*2 = 4096 floats (16 KB)

    const int tid   = threadIdx.x;
    const int lane  = tid & 31;
    const int w     = tid >> 5;
    const int warpM = w >> 1;       // 0..3  (32 rows each)
    const int warpN = w & 1;        // 0..1  (32 cols each)
    const int m0 = blockIdx.x * 128;
    const int n0 = blockIdx.y * 64;

    int rid[8];
#pragma unroll
    for (int i = 0; i < 8; i++) rid[i] = ids[m0 + i * 16 + (tid >> 4)];

    float acc[2][4][4];
#pragma unroll
    for (int mt = 0; mt < 2; mt++)
#pragma unroll
        for (int nt = 0; nt < 4; nt++)
#pragma unroll
            for (int r = 0; r < 4; r++) acc[mt][nt][r] = 0.0f;

#pragma unroll 1
    for (int pass = 0; pass < 2; pass++){
        const int k0 = pass * 64;

        // ---- fill A: 128 rows x 64 k (tf32), fragment-permuted ----
        {
            const int kq4 = tid & 15;            // which float4 within the 64-k row
#pragma unroll
            for (int i = 0; i < 8; i++){
                int row = i * 16 + (tid >> 4);
                float4 v = *(const float4*)(emb + rid[i] * 128 + k0 + kq4 * 4);
                int base = (((row >> 4) * 8 + (kq4 >> 1)) * 32 + (row & 7) * 4) * 4
                           + ((row >> 3) & 1) + 2 * (kq4 & 1);
                sA[base + 0*4] = to_tf32(v.x);
                sA[base + 1*4] = to_tf32(v.y);
                sA[base + 2*4] = to_tf32(v.z);
                sA[base + 3*4] = to_tf32(v.w);
            }
        }
        // ---- fill W: 64 rows x 64 k (tf32), fragment-permuted ----
        {
#pragma unroll
            for (int i = 0; i < 4; i++){
                int idx = i * 256 + tid;         // 0..1023
                int n   = idx >> 4;              // 0..63
                int kq4 = idx & 15;
                float4 v = *(const float4*)(wproj + (n0 + n) * 128 + k0 + kq4 * 4);
                int base = (((n >> 3) * 8 + (kq4 >> 1)) * 32 + (n & 7) * 4) * 2 + (kq4 & 1);
                sW[base + 0*2] = to_tf32(v.x);
                sW[base + 1*2] = to_tf32(v.y);
                sW[base + 2*2] = to_tf32(v.z);
                sW[base + 3*2] = to_tf32(v.w);
            }
        }
        __syncthreads();

#pragma unroll
        for (int k8 = 0; k8 < 8; k8++){
            float4 af[2];
#pragma unroll
            for (int mt = 0; mt < 2; mt++)
                af[mt] = *(const float4*)&sA[(((warpM * 2 + mt) * 8 + k8) * 32 + lane) * 4];
            float2 bf[4];
#pragma unroll
            for (int nt = 0; nt < 4; nt++)
                bf[nt] = *(const float2*)&sW[(((warpN * 4 + nt) * 8 + k8) * 32 + lane) * 2];
#pragma unroll
            for (int mt = 0; mt < 2; mt++)
#pragma unroll
                for (int nt = 0; nt < 4; nt++){
                    asm volatile(
                        "mma.sync.aligned.m16n8k8.row.col.f32.tf32.tf32.f32 "
                        "{%0,%1,%2,%3},{%4,%5,%6,%7},{%8,%9},{%0,%1,%2,%3};"
                        : "+f"(acc[mt][nt][0]), "+f"(acc[mt][nt][1]),
                          "+f"(acc[mt][nt][2]), "+f"(acc[mt][nt][3])
                        : "r"(__float_as_uint(af[mt].x)), "r"(__float_as_uint(af[mt].y)),
                          "r"(__float_as_uint(af[mt].z)), "r"(__float_as_uint(af[mt].w)),
                          "r"(__float_as_uint(bf[nt].x)), "r"(__float_as_uint(bf[nt].y)));
                }
        }
        __syncthreads();
    }

    // ---- epilogue: stage tile (SiLU applied for z half), then coalesced stores ----
    const bool is_x = (n0 < 256);
    float* sE = smem_all;                // reuse; 128 rows x stride 72 = 9216 floats
#pragma unroll
    for (int mt = 0; mt < 2; mt++)
#pragma unroll
        for (int nt = 0; nt < 4; nt++)
#pragma unroll
            for (int rh = 0; rh < 2; rh++){
                int ml = warpM * 32 + mt * 16 + (lane >> 2) + rh * 8;
                int nl = warpN * 32 + nt * 8 + (lane & 3) * 2;
                float v0 = acc[mt][nt][rh * 2 + 0];
                float v1 = acc[mt][nt][rh * 2 + 1];
                if (!is_x){ v0 = silu_f(v0); v1 = silu_f(v1); }
                *(float2*)&sE[ml * 72 + nl] = make_float2(v0, v1);
            }
    __syncthreads();
    {
        float* dst = is_x ? g_xcraw : g_gate;
        int ncol0  = is_x ? n0 : (n0 - 256);
#pragma unroll
        for (int i = 0; i < 8; i++){
            int idx = i * 256 + tid;         // 0..2047
            int row = idx >> 4;
            int q   = idx & 15;
            float4 v = *(const float4*)&sE[row * 72 + q * 4];
            *(float4*)(dst + (m0 + row) * 256 + ncol0 + q * 4) = v;
        }
    }
}

// ---------------- K2: depthwise causal conv + bias + SiLU (register ring over L-strip) ----------------
#define LCH 16
__global__ void __launch_bounds__(256) k2_conv(const float* __restrict__ conv_w,
                                               const float* __restrict__ conv_b)
{
    int gidx = blockIdx.x * 256 + threadIdx.x;   // Bsz * (Lsz/LCH) * 64 threads
    int d4 = gidx & 63;
    int lc = (gidx >> 6) & ((Lsz / LCH) - 1);
    int b  = gidx >> (6 + 7);                    // Lsz/LCH = 128 -> 7 bits
    int d  = d4 << 2;

    float w[4][4];
#pragma unroll
    for (int q = 0; q < 4; q++){
        float4 wq = __ldg((const float4*)(conv_w + (d + q) * 4));
        w[q][0] = wq.x; w[q][1] = wq.y; w[q][2] = wq.z; w[q][3] = wq.w;
    }
    float4 bb = __ldg((const float4*)(conv_b + d));

    const int l0 = lc * LCH;
    const int bl0 = b * Lsz + l0;
    float4 zero = make_float4(0.f, 0.f, 0.f, 0.f);
    float4 r1 = (l0 >= 3) ? *(const float4*)(g_xcraw + (bl0 - 3) * 256 + d) : zero;
    float4 r2 = (l0 >= 2) ? *(const float4*)(g_xcraw + (bl0 - 2) * 256 + d) : zero;
    float4 r3 = (l0 >= 1) ? *(const float4*)(g_xcraw + (bl0 - 1) * 256 + d) : zero;

#pragma unroll
    for (int i = 0; i < LCH; i++){
        float4 cur = *(const float4*)(g_xcraw + (bl0 + i) * 256 + d);
        float a0 = bb.x, a1 = bb.y, a2 = bb.z, a3 = bb.w;
        a0 = fmaf(w[0][0], r1.x, a0); a1 = fmaf(w[1][0], r1.y, a1);
        a2 = fmaf(w[2][0], r1.z, a2); a3 = fmaf(w[3][0], r1.w, a3);
        a0 = fmaf(w[0][1], r2.x, a0); a1 = fmaf(w[1][1], r2.y, a1);
        a2 = fmaf(w[2][1], r2.z, a2); a3 = fmaf(w[3][1], r2.w, a3);
        a0 = fmaf(w[0][2], r3.x, a0); a1 = fmaf(w[1][2], r3.y, a1);
        a2 = fmaf(w[2][2], r3.z, a2); a3 = fmaf(w[3][2], r3.w, a3);
        a0 = fmaf(w[0][3], cur.x, a0); a1 = fmaf(w[1][3], cur.y, a1);
        a2 = fmaf(w[2][3], cur.z, a2); a3 = fmaf(w[3][3], cur.w, a3);
        float4 o;
        o.x = silu_f(a0); o.y = silu_f(a1); o.z = silu_f(a2); o.w = silu_f(a3);
        *(float4*)(g_xc + (bl0 + i) * 256 + d) = o;
        r1 = r2; r2 = r3; r3 = cur;
    }
}

// ---------------- K3: x_proj (40x256) + dt_proj (256x8) + softplus; emit {delta,xc}/B/C ----------------
__global__ void __launch_bounds__(256) k3_xproj(const float* __restrict__ xpw,
                                                const float* __restrict__ dtw,
                                                const float* __restrict__ dtb)
{
    __shared__ __align__(16) float sw[40 * 256];
    __shared__ float sdbc[8][4][40];
    const int tid  = threadIdx.x;
    const int lane = tid & 31;
    const int wp   = tid >> 5;
    const int bl0  = (blockIdx.x * 8 + wp) * 4;

#pragma unroll
    for (int i = 0; i < 10; i++)
        ((float4*)sw)[i * 256 + tid] = ((const float4*)xpw)[i * 256 + tid];
    __syncthreads();

    float xcl[4][8];
#pragma unroll
    for (int p = 0; p < 4; p++)
#pragma unroll
        for (int k = 0; k < 8; k++)
            xcl[p][k] = g_xc[(bl0 + p) * 256 + k * 32 + lane];

#pragma unroll 8
    for (int j = 0; j < 40; j++){
        float wl[8];
#pragma unroll
        for (int k = 0; k < 8; k++) wl[k] = sw[j * 256 + k * 32 + lane];
        float s0 = 0.f, s1 = 0.f, s2 = 0.f, s3 = 0.f;
#pragma unroll
        for (int k = 0; k < 8; k++){
            s0 = fmaf(wl[k], xcl[0][k], s0);
            s1 = fmaf(wl[k], xcl[1][k], s1);
            s2 = fmaf(wl[k], xcl[2][k], s2);
            s3 = fmaf(wl[k], xcl[3][k], s3);
        }
#pragma unroll
        for (int off = 16; off; off >>= 1){
            s0 += __shfl_xor_sync(0xffffffffu, s0, off);
            s1 += __shfl_xor_sync(0xffffffffu, s1, off);
            s2 += __shfl_xor_sync(0xffffffffu, s2, off);
            s3 += __shfl_xor_sync(0xffffffffu, s3, off);
        }
        if (lane == 0){
            sdbc[wp][0][j] = s0; sdbc[wp][1][j] = s1;
            sdbc[wp][2][j] = s2; sdbc[wp][3][j] = s3;
        }
    }
    __syncwarp();

    if (lane < 16){
#pragma unroll
        for (int p = 0; p < 4; p++){
            g_Bm[(bl0 + p) * 16 + lane] = sdbc[wp][p][8  + lane];
            g_Cm[(bl0 + p) * 16 + lane] = sdbc[wp][p][24 + lane];
        }
    }

#pragma unroll
    for (int k = 0; k < 8; k++){
        int d = k * 32 + lane;
        float4 w0 = __ldg((const float4*)(dtw + d * 8));
        float4 w1 = __ldg((const float4*)(dtw + d * 8 + 4));
        float bias = __ldg(dtb + d);
#pragma unroll
        for (int p = 0; p < 4; p++){
            const float* dv = sdbc[wp][p];
            float t = bias;
            t = fmaf(w0.x, dv[0], t); t = fmaf(w0.y, dv[1], t);
            t = fmaf(w0.z, dv[2], t); t = fmaf(w0.w, dv[3], t);
            t = fmaf(w1.x, dv[4], t); t = fmaf(w1.y, dv[5], t);
            t = fmaf(w1.z, dv[6], t); t = fmaf(w1.w, dv[7], t);
            g_dxc[(bl0 + p) * 256 + d] = make_float2(softplus_f(t), xcl[p][k]);
        }
    }
}

// ---------------- K4: chunked selective scan, pass A (split-state, split accumulator) ----------------
// 2 threads per channel (8 states each). dA_n = e1^(n+1), e1 = exp(delta*A[d,0]).
// Each state-half accumulates its own gated partial; ONE shfl at chunk end combines.
__global__ void __launch_bounds__(256, 3) k4_scan(const float* __restrict__ A_log,
                                                  const float* __restrict__ Dvec)
{
    __shared__ __align__(16) float sB[CLEN * 16];
    __shared__ __align__(16) float sC[CLEN * 16];

    const int b   = blockIdx.x >> 6;         // 32 chunks * 2 channel-halves
    const int c   = (blockIdx.x >> 1) & 31;
    const int hb  = blockIdx.x & 1;          // channel-half block
    const int tid = threadIdx.x;
    const int dl  = tid >> 1;                // 0..127
    const int sh  = tid & 1;                 // state half
    const int d   = hb * 128 + dl;
    const int n0  = sh * 8;

    const float An0 = -__expf(__ldg(A_log + d * 16));
    bool pw_ok = true;
#pragma unroll
    for (int j = 0; j < 8; j++){
        float Ann = -__expf(__ldg(A_log + d * 16 + n0 + j));
        pw_ok = pw_ok && (fabsf(Ann / An0 - (float)(n0 + j + 1)) < 1e-3f);
    }
    const float Dd_eff = sh ? 0.0f : __ldg(Dvec + d);   // only half 0 adds the D term

    const int l0 = b * Lsz + c * CLEN;
    {
        const float4* gB = (const float4*)(g_Bm + l0 * 16);
        const float4* gC = (const float4*)(g_Cm + l0 * 16);
        ((float4*)sB)[tid] = gB[tid];
        ((float4*)sC)[tid] = gC[tid];
    }
    __syncthreads();

    float h[8], P[8], S[8];
#pragma unroll
    for (int j = 0; j < 8; j++){ h[j] = 0.0f; P[j] = 1.0f; S[j] = 0.0f; }
    float accl = 0.0f;

    int base = l0 * 256 + d;

    if (pw_ok){
        float2 pdx[4]; float pg[4];
#pragma unroll
        for (int q = 0; q < 4; q++){
            pdx[q] = g_dxc[base + q * 256];
            pg[q]  = __ldg(g_gate + base + q * 256);
        }
#pragma unroll 1
        for (int t = 0; t < CLEN; t += 4){
            float2 cdx[4]; float cg[4];
#pragma unroll
            for (int q = 0; q < 4; q++){ cdx[q] = pdx[q]; cg[q] = pg[q]; }
            int nb = base + 4 * 256;
            if (t + 4 < CLEN){
#pragma unroll
                for (int q = 0; q < 4; q++){
                    pdx[q] = g_dxc[nb + q * 256];
                    pg[q]  = __ldg(g_gate + nb + q * 256);
                }
            }
            float e1v[4];
#pragma unroll
            for (int q = 0; q < 4; q++) e1v[q] = __expf(cdx[q].x * An0);

#pragma unroll
            for (int q = 0; q < 4; q++){
                float gv  = cg[q];
                float xcv = cdx[q].y;
                float dxv = cdx[q].x * xcv;

                // powers e1^1..e1^8, then shift by e1^8 for the upper half
                float qp[8];
                qp[0] = e1v[q];
#pragma unroll
                for (int i = 1; i < 8; i++) qp[i] = qp[(i - 1) >> 1] * qp[i >> 1];
                float fac = sh ? qp[7] : 1.0f;

                float4 bb0 = ((const float4*)sB)[(t + q) * 4 + sh * 2 + 0];
                float4 bb1 = ((const float4*)sB)[(t + q) * 4 + sh * 2 + 1];
                float4 cc0 = ((const float4*)sC)[(t + q) * 4 + sh * 2 + 0];
                float4 cc1 = ((const float4*)sC)[(t + q) * 4 + sh * 2 + 1];
                float Bv[8] = {bb0.x, bb0.y, bb0.z, bb0.w, bb1.x, bb1.y, bb1.z, bb1.w};
                float Cv[8] = {cc0.x, cc0.y, cc0.z, cc0.w, cc1.x, cc1.y, cc1.z, cc1.w};

                float yloc = 0.0f;
#pragma unroll
                for (int j = 0; j < 8; j++){
                    float pj = qp[j] * fac;
                    P[j] *= pj;
                    h[j] = fmaf(pj, h[j], dxv * Bv[j]);
                    yloc = fmaf(h[j], Cv[j], yloc);
                    S[j] = fmaf(P[j], gv * Cv[j], S[j]);
                }
                accl = fmaf(gv, fmaf(xcv, Dd_eff, yloc), accl);   // half-partial
            }
            base = nb;
        }
    } else {
        // cold generic path (correctness only)
#pragma unroll 1
        for (int t = 0; t < CLEN; t++){
            float2 dxc  = g_dxc[base];
            float delta = dxc.x;
            float gv    = g_gate[base];
            float xcv   = dxc.y;
            float dxv   = delta * xcv;
            float yloc  = 0.0f;
#pragma unroll 4
            for (int j = 0; j < 8; j++){
                float An = -__expf(__ldg(A_log + d * 16 + n0 + j));
                float dA = __expf(delta * An);
                float Bn = sB[t * 16 + n0 + j];
                float Cn = sC[t * 16 + n0 + j];
                P[j] *= dA;
                h[j] = fmaf(dA, h[j], dxv * Bn);
                yloc = fmaf(h[j], Cn, yloc);
                S[j] = fmaf(P[j], gv * Cn, S[j]);
            }
            accl = fmaf(gv, fmaf(xcv, Dd_eff, yloc), accl);
            base += 256;
        }
    }

    // combine the two half-partials once per chunk
    accl += __shfl_xor_sync(0xffffffffu, accl, 1);

    const int ob = (b * 256 + d) * NCH + c;
    if (sh == 0) g_accl[ob] = accl;
    *(float4*)(g_P  + ob * 16 + n0)     = make_float4(P[0], P[1], P[2], P[3]);
    *(float4*)(g_P  + ob * 16 + n0 + 4) = make_float4(P[4], P[5], P[6], P[7]);
    *(float4*)(g_hl + ob * 16 + n0)     = make_float4(h[0], h[1], h[2], h[3]);
    *(float4*)(g_hl + ob * 16 + n0 + 4) = make_float4(h[4], h[5], h[6], h[7]);
    *(float4*)(g_S  + ob * 16 + n0)     = make_float4(S[0], S[1], S[2], S[3]);
    *(float4*)(g_S  + ob * 16 + n0 + 4) = make_float4(S[4], S[5], S[6], S[7]);
}

// ---------------- K5: chunk combine (sequential over 32 chunks per (b,d)) ----------------
__global__ void __launch_bounds__(256) k5_combine()
{
    int gid = blockIdx.x * 256 + threadIdx.x;   // (b,d): 0..4095
    float h[16];
#pragma unroll
    for (int n = 0; n < 16; n++) h[n] = 0.0f;
    float acc = 0.0f;
#pragma unroll 1
    for (int c = 0; c < NCH; c++){
        int base = gid * NCH + c;
        acc += g_accl[base];
        const float4* sp = (const float4*)(g_S  + base * 16);
        const float4* pp = (const float4*)(g_P  + base * 16);
        const float4* hp = (const float4*)(g_hl + base * 16);
#pragma unroll
        for (int q = 0; q < 4; q++){
            float4 sv = sp[q], pv = pp[q], hv = hp[q];
            acc = fmaf(h[q*4+0], sv.x, acc);
            acc = fmaf(h[q*4+1], sv.y, acc);
            acc = fmaf(h[q*4+2], sv.z, acc);
            acc = fmaf(h[q*4+3], sv.w, acc);
            h[q*4+0] = fmaf(pv.x, h[q*4+0], hv.x);
            h[q*4+1] = fmaf(pv.y, h[q*4+1], hv.y);
            h[q*4+2] = fmaf(pv.z, h[q*4+2], hv.z);
            h[q*4+3] = fmaf(pv.w, h[q*4+3], hv.w);
        }
    }
    g_acc[gid] = acc;
}

// ---------------- K6: out_proj + mean + classifier ----------------
__global__ void __launch_bounds__(128) k6_head(const float* __restrict__ opw,
                                               const float* __restrict__ clw,
                                               const float* __restrict__ clb,
                                               float* __restrict__ out)
{
    __shared__ float mvec[128];
    int b = blockIdx.x, j = threadIdx.x;
    float s = 0.0f;
    const float* ar = g_acc + b * 256;
#pragma unroll 8
    for (int e = 0; e < 256; e++) s = fmaf(ar[e], __ldg(opw + j * 256 + e), s);
    mvec[j] = s * (1.0f / 2048.0f);
    __syncthreads();
    if (j < 2){
        float t = __ldg(clb + j);
#pragma unroll 8
        for (int e = 0; e < 128; e++) t = fmaf(mvec[e], __ldg(clw + j * 128 + e), t);
        out[b * 2 + j] = t;
    }
}

// ---------------- launch ----------------
extern "C" void kernel_launch(void* const* d_in, const int* in_sizes, int n_in,
                              void* d_out, int out_size)
{
    const int*   ids  = (const int*)  d_in[0];
    const float* emb  = (const float*)d_in[1];
    const float* ipw  = (const float*)d_in[2];
    const float* cw   = (const float*)d_in[3];
    const float* cb   = (const float*)d_in[4];
    const float* xpw  = (const float*)d_in[5];
    const float* dtw  = (const float*)d_in[6];
    const float* dtb  = (const float*)d_in[7];
    const float* alog = (const float*)d_in[8];
    const float* dvec = (const float*)d_in[9];
    const float* opw  = (const float*)d_in[10];
    const float* clw  = (const float*)d_in[11];
    const float* clb  = (const float*)d_in[12];
    float* out = (float*)d_out;

    dim3 g1(BLn / 128, 8);   // 256 m-tiles x 8 n-tiles of 64
    k1_inproj<<<g1, 256>>>(ids, emb, ipw);
    k2_conv<<<(Bsz * (Lsz / LCH) * 64) / 256, 256>>>(cw, cb);
    k3_xproj<<<BLn / 32, 256>>>(xpw, dtw, dtb);
    k4_scan<<<Bsz * NCH * 2, 256>>>(alog, dvec);
    k5_combine<<<(Bsz * DI) / 256, 256>>>();
    k6_head<<<Bsz, 128>>>(opw, clw, clb, out);
}